// round 6
// baseline (speedup 1.0000x reference)
#include <cuda_runtime.h>
#include <math.h>

// mask [8,256,256] fp32 -> EDT (separable squared) -> normalize by global max -> sigmoid.
// 64 blocks x 1024 threads: 8 blocks/image, 32 columns/block. Each block builds its
// ENTIRE image's row-bitmap redundantly in smem (kills grid barrier #1); only one
// grid sync remains (global max), with 64 balanced arrivals.
constexpr int B_ = 8;
constexpr int H_ = 256;
constexpr int W_ = 256;
constexpr float THR   = 0.5f;
constexpr float INF_F = 1e10f;

constexpr int BPI  = 8;            // blocks per image
constexpr int NBLK = B_ * BPI;     // 64
constexpr int NTHR = 1024;
constexpr int CPB  = 32;           // columns per block

__device__ unsigned g_max;         // max d2 (float bits, nonneg)
__device__ unsigned g_cnt0, g_cnt1;

__global__ __launch_bounds__(NTHR) void k_all(const float* __restrict__ mask,
                                              float* __restrict__ out) {
    const int blk  = blockIdx.x;
    const int t    = threadIdx.x;
    const int lane = t & 31;
    const int warp = t >> 5;
    const int b    = blk >> 3;                 // image
    const int x0   = (blk & 7) * CPB;          // column tile base

    __shared__ unsigned       bs[H_ * 8];      // 8KB: full image row-bitmaps [y][wi]
    __shared__ unsigned short tmp[H_ * CPB];   // 16KB: pass-1 distances [y][c]
    __shared__ float          red[32];
    __shared__ float          s_scale;

    // ---- Phase A: build full-image bitmap from mask (block-local, no grid sync)
    // 512 chunks of 128 contiguous pixels; warp per chunk; float4 per lane.
    const float* mimg = mask + b * H_ * W_;
    #pragma unroll
    for (int it = 0; it < 16; ++it) {
        const int chunk = it * 32 + warp;      // 0..511
        const int r = chunk >> 1;              // row
        const int h = chunk & 1;               // which 128-col half
        const float4 v = reinterpret_cast<const float4*>(mimg + r * W_ + h * 128)[lane];
        unsigned nib = (v.x > THR ? 1u : 0u) | (v.y > THR ? 2u : 0u)
                     | (v.z > THR ? 4u : 0u) | (v.w > THR ? 8u : 0u);
        unsigned val = nib << ((lane & 7) * 4);
        val |= __shfl_xor_sync(0xffffffffu, val, 1);
        val |= __shfl_xor_sync(0xffffffffu, val, 2);
        val |= __shfl_xor_sync(0xffffffffu, val, 4);
        if ((lane & 7) == 0) bs[r * 8 + h * 4 + (lane >> 3)] = val;
    }
    __syncthreads();

    // ---- Pass 1: nearest set bit to x in each row's bitmap
    const int c  = t & 31;                     // column in tile (== lane)
    const int yb = t >> 5;                     // base row (0..31)
    const int x  = x0 + c;
    const int wx = x >> 5;                     // == x0>>5 (uniform per block)
    const unsigned mLo = 0xFFFFFFFFu >> (31 - (x & 31));
    const unsigned mHi = 0xFFFFFFFFu << (x & 31);

    #pragma unroll
    for (int i = 0; i < 8; ++i) {
        const int y = yb + i * 32;
        const unsigned* row = bs + y * 8;      // lanes share y -> broadcast loads
        const unsigned wcur = row[wx];
        int dl = 1 << 29, dr = 1 << 29;
        unsigned m = wcur & mLo;
        if (m) {
            dl = x - (wx * 32 + 31 - __clz(m));
        } else {
            #pragma unroll 1
            for (int wi = wx - 1; wi >= 0; --wi) {
                const unsigned w = row[wi];
                if (w) { dl = x - (wi * 32 + 31 - __clz(w)); break; }
            }
        }
        m = wcur & mHi;
        if (m) {
            dr = wx * 32 + (__ffs(m) - 1) - x;
        } else {
            #pragma unroll 1
            for (int wi = wx + 1; wi < 8; ++wi) {
                const unsigned w = row[wi];
                if (w) { dr = wi * 32 + (__ffs(w) - 1) - x; break; }
            }
        }
        const int d = min(dl, dr);
        tmp[y * CPB + c] = (d <= 255) ? (unsigned short)d : (unsigned short)0xFFFF;
    }
    __syncthreads();

    // ---- Pass 2: d2 = min_k ( k^2 + tmp[y+-k]^2 ), exact prune (tmp^2 >= 0)
    float bestv[8];
    float lmax = 0.0f;
    #pragma unroll
    for (int i = 0; i < 8; ++i) {
        const int y = yb + i * 32;
        const int d0 = tmp[y * CPB + c];
        float best = (d0 == 0xFFFF) ? INF_F : (float)(d0 * d0);
        #pragma unroll 1
        for (int k = 1; k < H_; ++k) {
            const float kk = (float)(k * k);
            if (kk >= best) break;
            const int ym = y - k;
            if (ym >= 0) {
                const int dm = tmp[ym * CPB + c];
                best = fminf(best, kk + ((dm == 0xFFFF) ? INF_F : (float)(dm * dm)));
            }
            const int yp = y + k;
            if (yp < H_) {
                const int dp = tmp[yp * CPB + c];
                best = fminf(best, kk + ((dp == 0xFFFF) ? INF_F : (float)(dp * dp)));
            }
        }
        bestv[i] = best;
        lmax = fmaxf(lmax, best);
    }

    // ---- Block max -> global atomic -> single grid sync (64 arrivals)
    #pragma unroll
    for (int off = 16; off; off >>= 1)
        lmax = fmaxf(lmax, __shfl_xor_sync(0xffffffffu, lmax, off));
    if (lane == 0) red[warp] = lmax;
    __syncthreads();
    if (t == 0) {
        float bm = red[0];
        #pragma unroll
        for (int i = 1; i < 32; ++i) bm = fmaxf(bm, red[i]);
        atomicMax(&g_max, __float_as_uint(bm));
        __threadfence();
        atomicAdd(&g_cnt0, 1u);
        while (__ldcg(&g_cnt0) < (unsigned)NBLK) __nanosleep(20);
        __threadfence();
        s_scale = 50.0f / (sqrtf(__uint_as_float(__ldcg(&g_max))) + 1.0f);
    }
    __syncthreads();
    const float s = s_scale;

    // ---- Epilogue: coalesced stores (warp = 32 consecutive columns)
    float* obase = out + b * H_ * W_ + x0;
    #pragma unroll
    for (int i = 0; i < 8; ++i) {
        const int y = yb + i * 32;
        obase[y * W_ + c] = 2.0f / (1.0f + __expf(sqrtf(bestv[i]) * s));
    }

    // ---- Reset for next graph replay: only after ALL blocks passed the spin
    __syncthreads();
    if (t == 0) {
        const unsigned old = atomicAdd(&g_cnt1, 1u);
        if (old == (unsigned)(NBLK - 1)) {
            g_cnt0 = 0u; g_cnt1 = 0u; g_max = 0u;
        }
    }
}

extern "C" void kernel_launch(void* const* d_in, const int* in_sizes, int n_in,
                              void* d_out, int out_size) {
    const float* mask = (const float*)d_in[0];
    float* out = (float*)d_out;
    k_all<<<NBLK, NTHR>>>(mask, out);
}

// round 7
// speedup vs baseline: 1.2054x; 1.2054x over previous
#include <cuda_runtime.h>
#include <math.h>

// mask [8,256,256] fp32 -> EDT (separable squared) -> normalize by global max -> sigmoid.
// 3-kernel pipeline, NO grid spin barriers (stream order is the sync):
//   k_row: per-row bitmaps via ballot (registers only) + nearest-set-bit pass -> tmp u16
//   k_col: column min-plus with exact prune -> d2, per-block atomicMax
//   k_fin: float4 sigmoid epilogue using global max
constexpr int B_ = 8;
constexpr int H_ = 256;
constexpr int W_ = 256;
constexpr int NT = B_ * H_ * W_;
constexpr float THR   = 0.5f;
constexpr float INF_F = 1e10f;
constexpr int BIG = 1 << 29;

__device__ unsigned short g_tmp[NT];   // pass-1 distances (0xFFFF = empty row)
__device__ float          g_d2[NT];    // squared distances
__device__ unsigned       g_max;       // max d2 (float bits, nonneg)

// ---------------------------------------------------------------------------
// k_row: 256 blocks x 256 thr. Warp handles one row (row = blk*8 + warp).
// 8 ballots give every lane the full 256-bit row bitmap in registers; the
// nearest-set-bit scan is fully unrolled (word index is compile-time).
__global__ __launch_bounds__(256) void k_row(const float* __restrict__ mask) {
    const int lane = threadIdx.x & 31;
    const int warp = threadIdx.x >> 5;
    const int row  = blockIdx.x * 8 + warp;        // b*H + y
    const float* mrow = mask + row * W_;

    if (blockIdx.x == 0 && threadIdx.x == 0) g_max = 0u;   // reset for this replay

    unsigned w[8];
    #pragma unroll
    for (int j = 0; j < 8; ++j)
        w[j] = __ballot_sync(0xffffffffu, mrow[j * 32 + lane] > THR);

    unsigned short* trow = g_tmp + row * W_;
    const unsigned mLo = 0xFFFFFFFFu >> (31 - lane);
    const unsigned mHi = 0xFFFFFFFFu << lane;

    #pragma unroll
    for (int j = 0; j < 8; ++j) {                  // pixel x = 32*j + lane, wx == j
        int dl = BIG, dr = BIG;
        unsigned m = w[j] & mLo;                   // bits <= x in own word
        if (m) dl = lane - (31 - __clz(m));
        #pragma unroll
        for (int wi = j - 1; wi >= 0; --wi)        // compile-time indices
            if (dl == BIG) {
                const unsigned ww = w[wi];
                if (ww) dl = (j - wi) * 32 + lane - (31 - __clz(ww));
            }
        m = w[j] & mHi;                            // bits >= x in own word
        if (m) dr = (__ffs(m) - 1) - lane;
        #pragma unroll
        for (int wi = j + 1; wi < 8; ++wi)
            if (dr == BIG) {
                const unsigned ww = w[wi];
                if (ww) dr = (wi - j) * 32 + (__ffs(ww) - 1) - lane;
            }
        const int d = min(dl, dr);
        trow[j * 32 + lane] = (d <= 255) ? (unsigned short)d : (unsigned short)0xFFFF;
    }
}

// ---------------------------------------------------------------------------
// k_col: 256 blocks x 256 thr. Block = (image b, 8-column tile x0).
// d2[y] = min_k ( k^2 + tmp[y+-k]^2 ), exact prune at k^2 >= best (tmp^2 >= 0).
__global__ __launch_bounds__(256) void k_col() {
    const int blk = blockIdx.x;
    const int b   = blk >> 5;
    const int x0  = (blk & 31) * 8;
    const int t   = threadIdx.x;

    __shared__ unsigned short tmp_s[H_ * 8];       // [y][c], 4KB
    // thread t loads row y=t's 8 u16 (16B, aligned)
    const uint4 v = *reinterpret_cast<const uint4*>(g_tmp + (b * H_ + t) * W_ + x0);
    *reinterpret_cast<uint4*>(tmp_s + t * 8) = v;
    __syncthreads();

    const int c  = t & 7;
    const int yb = t >> 3;                         // 0..31
    float lmax = 0.0f;

    #pragma unroll
    for (int i = 0; i < 8; ++i) {
        const int y = yb + i * 32;
        const int d0 = tmp_s[y * 8 + c];
        float best = (d0 == 0xFFFF) ? INF_F : (float)(d0 * d0);
        #pragma unroll 1
        for (int k = 1; k < H_; ++k) {
            const float kk = (float)(k * k);
            if (kk >= best) break;
            const int ym = y - k;
            if (ym >= 0) {
                const int dm = tmp_s[ym * 8 + c];
                best = fminf(best, kk + ((dm == 0xFFFF) ? INF_F : (float)(dm * dm)));
            }
            const int yp = y + k;
            if (yp < H_) {
                const int dp = tmp_s[yp * 8 + c];
                best = fminf(best, kk + ((dp == 0xFFFF) ? INF_F : (float)(dp * dp)));
            }
        }
        g_d2[(b * H_ + y) * W_ + x0 + c] = best;
        lmax = fmaxf(lmax, best);
    }

    // block max -> one atomic
    #pragma unroll
    for (int off = 16; off; off >>= 1)
        lmax = fmaxf(lmax, __shfl_xor_sync(0xffffffffu, lmax, off));
    __shared__ float red[8];
    if ((t & 31) == 0) red[t >> 5] = lmax;
    __syncthreads();
    if (t == 0) {
        float bm = red[0];
        #pragma unroll
        for (int i = 1; i < 8; ++i) bm = fmaxf(bm, red[i]);
        atomicMax(&g_max, __float_as_uint(bm));
    }
}

// ---------------------------------------------------------------------------
// k_fin: 512 blocks x 256 thr, float4. out = 2 / (1 + exp(sqrt(d2)*50/(sqrt(max)+1)))
__global__ __launch_bounds__(256) void k_fin(float* __restrict__ out) {
    const int i = blockIdx.x * 256 + threadIdx.x;
    const float md = sqrtf(__uint_as_float(__ldcg(&g_max))) + 1.0f;
    const float s  = 50.0f / md;
    const float4 d2 = reinterpret_cast<const float4*>(g_d2)[i];
    float4 o;
    o.x = 2.0f / (1.0f + __expf(sqrtf(d2.x) * s));
    o.y = 2.0f / (1.0f + __expf(sqrtf(d2.y) * s));
    o.z = 2.0f / (1.0f + __expf(sqrtf(d2.z) * s));
    o.w = 2.0f / (1.0f + __expf(sqrtf(d2.w) * s));
    reinterpret_cast<float4*>(out)[i] = o;
}

// ---------------------------------------------------------------------------
extern "C" void kernel_launch(void* const* d_in, const int* in_sizes, int n_in,
                              void* d_out, int out_size) {
    const float* mask = (const float*)d_in[0];
    float* out = (float*)d_out;
    k_row<<<B_ * H_ / 8, 256>>>(mask);
    k_col<<<B_ * (W_ / 8), 256>>>();
    k_fin<<<NT / 4 / 256, 256>>>(out);
}

// round 8
// speedup vs baseline: 1.3466x; 1.1172x over previous
#include <cuda_runtime.h>
#include <math.h>

// mask [8,256,256] fp32 -> EDT (separable squared) -> normalize by global max -> sigmoid.
// 2-kernel pipeline:
//   k_row: warp-per-row; 2x LDG.128 + nibble-shfl bitmap; nearest-set-bit -> g_tmp u16.
//          Also resets barrier counter + global max (stream-ordered => graph-safe).
//   k_fuse: column min-plus with exact prune (d2 in registers), per-block atomicMax,
//           single 256-arrival spin barrier, fused sigmoid epilogue. No d2 round-trip.
constexpr int B_ = 8;
constexpr int H_ = 256;
constexpr int W_ = 256;
constexpr int NT = B_ * H_ * W_;
constexpr float THR   = 0.5f;
constexpr float INF_F = 1e10f;
constexpr int BIG = 1 << 29;
constexpr int NBLK2 = 256;

__device__ unsigned short g_tmp[NT];   // pass-1 distances (0xFFFF = empty row)
__device__ unsigned       g_max;       // max d2 (float bits, nonneg)
__device__ unsigned       g_cnt;       // barrier counter

// ---------------------------------------------------------------------------
// k_row: 256 blocks x 256 thr; warp handles one row.
__global__ __launch_bounds__(256) void k_row(const float* __restrict__ mask) {
    const int lane = threadIdx.x & 31;
    const int warp = threadIdx.x >> 5;
    const int row  = blockIdx.x * 8 + warp;        // b*H + y

    if (blockIdx.x == 0 && threadIdx.x == 0) { g_cnt = 0u; g_max = 0u; }

    // Load whole row: 2 x float4 per lane (pixels 4*lane.. and 128+4*lane..)
    const float4* row4 = reinterpret_cast<const float4*>(mask + row * W_);
    const float4 a = row4[lane];
    const float4 bq = row4[lane + 32];

    // nibble -> 32-bit words via shfl-or; lanes 8g..8g+7 hold word g
    unsigned va = ((a.x > THR ? 1u : 0u) | (a.y > THR ? 2u : 0u)
                 | (a.z > THR ? 4u : 0u) | (a.w > THR ? 8u : 0u)) << ((lane & 7) * 4);
    unsigned vb = ((bq.x > THR ? 1u : 0u) | (bq.y > THR ? 2u : 0u)
                 | (bq.z > THR ? 4u : 0u) | (bq.w > THR ? 8u : 0u)) << ((lane & 7) * 4);
    va |= __shfl_xor_sync(0xffffffffu, va, 1);
    vb |= __shfl_xor_sync(0xffffffffu, vb, 1);
    va |= __shfl_xor_sync(0xffffffffu, va, 2);
    vb |= __shfl_xor_sync(0xffffffffu, vb, 2);
    va |= __shfl_xor_sync(0xffffffffu, va, 4);
    vb |= __shfl_xor_sync(0xffffffffu, vb, 4);

    unsigned w[8];
    #pragma unroll
    for (int j = 0; j < 4; ++j) {
        w[j]     = __shfl_sync(0xffffffffu, va, j * 8);
        w[4 + j] = __shfl_sync(0xffffffffu, vb, j * 8);
    }

    unsigned short* trow = g_tmp + row * W_;
    const unsigned mLo = 0xFFFFFFFFu >> (31 - lane);
    const unsigned mHi = 0xFFFFFFFFu << lane;

    #pragma unroll
    for (int j = 0; j < 8; ++j) {                  // pixel x = 32*j + lane
        int dl = BIG, dr = BIG;
        unsigned m = w[j] & mLo;
        if (m) dl = lane - (31 - __clz(m));
        #pragma unroll
        for (int wi = j - 1; wi >= 0; --wi)
            if (dl == BIG) {
                const unsigned ww = w[wi];
                if (ww) dl = (j - wi) * 32 + lane - (31 - __clz(ww));
            }
        m = w[j] & mHi;
        if (m) dr = (__ffs(m) - 1) - lane;
        #pragma unroll
        for (int wi = j + 1; wi < 8; ++wi)
            if (dr == BIG) {
                const unsigned ww = w[wi];
                if (ww) dr = (wi - j) * 32 + (__ffs(ww) - 1) - lane;
            }
        const int d = min(dl, dr);
        trow[j * 32 + lane] = (d <= 255) ? (unsigned short)d : (unsigned short)0xFFFF;
    }
}

// ---------------------------------------------------------------------------
// k_fuse: 256 blocks x 256 thr. Block = (image b, 8-column tile x0).
// Pass 2 in registers -> block max -> single grid spin -> sigmoid store.
__global__ __launch_bounds__(256) void k_fuse(float* __restrict__ out) {
    const int blk = blockIdx.x;
    const int b   = blk >> 5;
    const int x0  = (blk & 31) * 8;
    const int t   = threadIdx.x;

    __shared__ float tmp2[H_ * 8];                 // pre-squared pass-1 values, 8KB
    __shared__ float red[8];
    __shared__ float s_scale;

    // thread t loads row y=t's 8 u16 (16B aligned), converts to squared float
    {
        const uint4 v = *reinterpret_cast<const uint4*>(g_tmp + (b * H_ + t) * W_ + x0);
        const unsigned short* u = reinterpret_cast<const unsigned short*>(&v);
        #pragma unroll
        for (int cc = 0; cc < 8; ++cc) {
            const unsigned d = u[cc];
            tmp2[t * 8 + cc] = (d == 0xFFFFu) ? INF_F : (float)(d * d);
        }
    }
    __syncthreads();

    const int c  = t & 7;
    const int yb = t >> 3;                         // 0..31
    float bestv[8];
    float lmax = 0.0f;

    #pragma unroll
    for (int i = 0; i < 8; ++i) {
        const int y = yb + i * 32;
        float best = tmp2[y * 8 + c];
        #pragma unroll 1
        for (int k = 1; k < H_; ++k) {
            const float kk = (float)(k * k);
            if (kk >= best) break;                 // exact prune (tmp2 >= 0)
            const int ym = y - k;
            if (ym >= 0) best = fminf(best, kk + tmp2[ym * 8 + c]);
            const int yp = y + k;
            if (yp < H_) best = fminf(best, kk + tmp2[yp * 8 + c]);
        }
        bestv[i] = best;
        lmax = fmaxf(lmax, best);
    }

    // block max -> global atomic -> single grid barrier (atomics overlap compute skew)
    #pragma unroll
    for (int off = 16; off; off >>= 1)
        lmax = fmaxf(lmax, __shfl_xor_sync(0xffffffffu, lmax, off));
    if ((t & 31) == 0) red[t >> 5] = lmax;
    __syncthreads();
    if (t == 0) {
        float bm = red[0];
        #pragma unroll
        for (int i = 1; i < 8; ++i) bm = fmaxf(bm, red[i]);
        atomicMax(&g_max, __float_as_uint(bm));
        __threadfence();
        atomicAdd(&g_cnt, 1u);
        while (__ldcg(&g_cnt) < (unsigned)NBLK2) __nanosleep(20);
        __threadfence();
        s_scale = 50.0f / (sqrtf(__uint_as_float(__ldcg(&g_max))) + 1.0f);
    }
    __syncthreads();
    const float s = s_scale;

    // fused epilogue straight from registers
    float* obase = out + b * H_ * W_ + x0;
    #pragma unroll
    for (int i = 0; i < 8; ++i) {
        const int y = yb + i * 32;
        obase[y * W_ + c] = 2.0f / (1.0f + __expf(sqrtf(bestv[i]) * s));
    }
}

// ---------------------------------------------------------------------------
extern "C" void kernel_launch(void* const* d_in, const int* in_sizes, int n_in,
                              void* d_out, int out_size) {
    const float* mask = (const float*)d_in[0];
    float* out = (float*)d_out;
    k_row<<<B_ * H_ / 8, 256>>>(mask);
    k_fuse<<<NBLK2, 256>>>(out);
}